// round 14
// baseline (speedup 1.0000x reference)
#include <cuda_runtime.h>
#include <cstdint>

// Segment-sum: out[src[e], f] += edge_w[e, f], F=16 (f32), E=3.2M, N=100k.
// Scatter is pinned at the L2/LTS atomic-RMW byte wall (~50us, proven
// invariant across LSU-RED / TMA-bulk / hybrid). This round fuses the
// output-zeroing into the scatter kernel behind a device-side ticket
// barrier, eliminating the separate zero kernel + launch gap (~3.4us).

static constexpr int F = 16;
static constexpr int THREADS = 256;

// Monotonic across graph replays; never reset (epoch via ticket arithmetic).
__device__ unsigned long long g_done = 0ULL;

__device__ __forceinline__ void red_v4(float* dst, float4 w) {
    asm volatile("red.global.add.v4.f32 [%0], {%1, %2, %3, %4};"
                 :: "l"(dst), "f"(w.x), "f"(w.y), "f"(w.z), "f"(w.w)
                 : "memory");
}

__global__ void __launch_bounds__(THREADS, 8) fused_scatter_kernel(
        const int* __restrict__ src,
        const float4* __restrict__ w4,
        float* __restrict__ out,
        int total,            // E*4 quad-items
        int n_out_vec) {      // N*16/4 float4s
    const int nthreads = gridDim.x * THREADS;
    const int gtid = blockIdx.x * THREADS + threadIdx.x;

    // ---- phase 1: distributed zero of the poisoned output ----
    float4* outv = (float4*)out;
    const float4 z = make_float4(0.f, 0.f, 0.f, 0.f);
    for (int i = gtid; i < n_out_vec; i += nthreads) outv[i] = z;
    __threadfence();

    // ---- device-side grid barrier (ticket; all CTAs are co-resident by
    //      __launch_bounds__(256,8) + occupancy-clamped grid) ----
    if (threadIdx.x == 0) {
        unsigned long long ticket = atomicAdd(&g_done, 1ULL);
        unsigned long long target =
            ticket - (ticket % (unsigned long long)gridDim.x)
                   + (unsigned long long)gridDim.x;
        unsigned long long v;
        do {
            asm volatile("ld.acquire.gpu.global.u64 %0, [%1];"
                         : "=l"(v) : "l"(&g_done) : "memory");
        } while (v < target);
    }
    __syncthreads();

    // ---- phase 2: scatter (R2-proven 4-batch structure, grid-strided) ----
    const int G = nthreads;                 // sub-batch stride
    for (int base = gtid; base < total; base += 4 * G) {
        const int i0 = base;
        const int i1 = base + G;
        const int i2 = base + 2 * G;
        const int i3 = base + 3 * G;

        int s0 = 0, s1 = 0, s2 = 0, s3 = 0;
        if (i0 < total) s0 = __ldg(&src[i0 >> 2]);
        if (i1 < total) s1 = __ldg(&src[i1 >> 2]);
        if (i2 < total) s2 = __ldg(&src[i2 >> 2]);
        if (i3 < total) s3 = __ldg(&src[i3 >> 2]);

        float4 w0, w1, w2, w3;
        if (i0 < total) w0 = __ldcs(&w4[i0]);
        if (i1 < total) w1 = __ldcs(&w4[i1]);
        if (i2 < total) w2 = __ldcs(&w4[i2]);
        if (i3 < total) w3 = __ldcs(&w4[i3]);

        if (i0 < total) red_v4(out + (size_t)s0 * F + (i0 & 3) * 4, w0);
        if (i1 < total) red_v4(out + (size_t)s1 * F + (i1 & 3) * 4, w1);
        if (i2 < total) red_v4(out + (size_t)s2 * F + (i2 & 3) * 4, w2);
        if (i3 < total) red_v4(out + (size_t)s3 * F + (i3 & 3) * 4, w3);
    }
}

extern "C" void kernel_launch(void* const* d_in, const int* in_sizes, int n_in,
                              void* d_out, int out_size) {
    const int* edge  = (const int*)d_in[0];        // [2, E]; row 0 = src
    const float4* w4 = (const float4*)d_in[1];     // [E, 16] f32 == [E*4] float4
    float* out       = (float*)d_out;              // [N, 16] f32

    const int E = in_sizes[1] / F;                 // 3,200,000
    const int total = E * 4;                       // 12.8M quad-items
    const int n_out_vec = out_size / 4;            // 400,000 float4s

    // Exactly-resident grid: clamp by the real occupancy of the compiled
    // kernel (host-side query; runs once during graph capture, not captured).
    int dev = 0, nsm = 148;
    cudaGetDevice(&dev);
    cudaDeviceGetAttribute(&nsm, cudaDevAttrMultiProcessorCount, dev);
    int occ = 8;
    cudaOccupancyMaxActiveBlocksPerMultiprocessor(
        &occ, fused_scatter_kernel, THREADS, 0);
    if (occ < 1) occ = 1;
    if (occ > 8) occ = 8;
    const int grid = nsm * occ;                    // all CTAs co-resident

    fused_scatter_kernel<<<grid, THREADS>>>(edge, w4, out, total, n_out_vec);
}

// round 15
// speedup vs baseline: 1.1272x; 1.1272x over previous
#include <cuda_runtime.h>
#include <cstdint>

// Segment-sum: out[src[e], f] += edge_w[e, f], F=16 (f32), E=3.2M, N=100k.
//
// Final form. Evidence from R1-R14: the scatter is pinned at the L2/LTS
// atomic-RMW byte wall (~50us) — invariant across LSU-RED, TMA bulk-reduce,
// hybrid engine splits, MLP batching, PDL, and persistent variants. The
// one-shot many-block RED form is fastest because fresh CTAs (load phase)
// pipeline against retiring CTAs (RED drain) in the LSU/L1tex queues;
// persistent loops serialize load->RED per warp and lose ~10%.
//
// This round: keep the proven R2 scatter byte-identical; trim the zero
// kernel to a single-wave grid-stride launch (fewer block launches).

static constexpr int F = 16;

__global__ void __launch_bounds__(256) zero_out_kernel(
        float4* __restrict__ out, int n_vec) {
    const int G = blockDim.x * gridDim.x;
    for (int i = blockIdx.x * blockDim.x + threadIdx.x; i < n_vec; i += G)
        out[i] = make_float4(0.f, 0.f, 0.f, 0.f);
}

__device__ __forceinline__ void red_v4(float* dst, float4 w) {
    asm volatile("red.global.add.v4.f32 [%0], {%1, %2, %3, %4};"
                 :: "l"(dst), "f"(w.x), "f"(w.y), "f"(w.z), "f"(w.w)
                 : "memory");
}

__global__ void __launch_bounds__(256) scatter_add_kernel(
        const int* __restrict__ src,
        const float4* __restrict__ w4,
        float* __restrict__ out,
        int total) {                      // total = E*4 quad-items
    const int G = blockDim.x * gridDim.x;
    const int t = blockIdx.x * blockDim.x + threadIdx.x;

    const int i0 = t;
    const int i1 = t + G;
    const int i2 = t + 2 * G;
    const int i3 = t + 3 * G;

    // ---- all index loads (4B, broadcast within each edge's 4 lanes) ----
    int s0 = 0, s1 = 0, s2 = 0, s3 = 0;
    if (i0 < total) s0 = __ldg(&src[i0 >> 2]);
    if (i1 < total) s1 = __ldg(&src[i1 >> 2]);
    if (i2 < total) s2 = __ldg(&src[i2 >> 2]);
    if (i3 < total) s3 = __ldg(&src[i3 >> 2]);

    // ---- all payload loads (16B, streaming / evict-first) ----
    float4 w0, w1, w2, w3;
    if (i0 < total) w0 = __ldcs(&w4[i0]);
    if (i1 < total) w1 = __ldcs(&w4[i1]);
    if (i2 < total) w2 = __ldcs(&w4[i2]);
    if (i3 < total) w3 = __ldcs(&w4[i3]);

    // ---- reductions (4 lanes cover one 64B row -> coalesced RED group) ----
    if (i0 < total) red_v4(out + (size_t)s0 * F + (i0 & 3) * 4, w0);
    if (i1 < total) red_v4(out + (size_t)s1 * F + (i1 & 3) * 4, w1);
    if (i2 < total) red_v4(out + (size_t)s2 * F + (i2 & 3) * 4, w2);
    if (i3 < total) red_v4(out + (size_t)s3 * F + (i3 & 3) * 4, w3);
}

extern "C" void kernel_launch(void* const* d_in, const int* in_sizes, int n_in,
                              void* d_out, int out_size) {
    const int* edge  = (const int*)d_in[0];        // [2, E]; row 0 = src
    const float4* w4 = (const float4*)d_in[1];     // [E, 16] f32 == [E*4] float4
    float* out       = (float*)d_out;              // [N, 16] f32

    const int E = in_sizes[1] / F;                 // 3,200,000
    const int n_out_vec = out_size / 4;            // 400,000 float4s

    // 1) zero the poisoned output: one wave, grid-strided (~6 st.128/thread)
    zero_out_kernel<<<264, 256>>>((float4*)d_out, n_out_vec);

    // 2) vectorized scatter-add, 4 items/thread (proven-best structure)
    {
        int total = E * 4;                          // 12.8M quad-items
        int threads = 256;
        int blocks = (total + threads * 4 - 1) / (threads * 4);  // 12500
        scatter_add_kernel<<<blocks, threads>>>(edge, w4, out, total);
    }
}